// round 16
// baseline (speedup 1.0000x reference)
#include <cuda_runtime.h>
#include <cstdint>

#define NB   4
#define IC   3
#define OC   16
#define ODIM 127
#define H_STR   128
#define D_STR   (128*128)
#define C_STR   (128*128*128)
#define O_HSTR  127
#define O_DSTR  (127*127)
#define O_CSTR  (127*127*127)

typedef unsigned long long ull;

// Folded weights, scalar layout: [ic][kh][kd][kw][oc]
__device__ float g_wS[3][2][2][2][16];
__device__ float g_fbS[16];

__device__ __forceinline__ ull fma2(ull a, ull b, ull c) {
    ull d;
    asm("fma.rn.f32x2 %0, %1, %2, %3;" : "=l"(d) : "l"(a), "l"(b), "l"(c));
    return d;
}
__device__ __forceinline__ ull pack2(float lo, float hi) {
    ull d;
    asm("mov.b64 %0, {%1, %2};" : "=l"(d) : "f"(lo), "f"(hi));
    return d;
}
__device__ __forceinline__ float2 unpack2(ull v) {
    float2 r;
    asm("mov.b64 {%0, %1}, %2;" : "=f"(r.x), "=f"(r.y) : "l"(v));
    return r;
}

// Fold ConvTranspose(k3,s2,p1)+AvgPool(2) -> 2x2x2 conv, with scales.
__global__ void prep_kernel(const float* __restrict__ cw,
                            const float* __restrict__ cb,
                            const float* __restrict__ eb) {
    int t = threadIdx.x;
    if (t >= 384) return;
    int oc = t & 15;
    int kw = (t >> 4) & 1;
    int kd = (t >> 5) & 1;
    int kh = (t >> 6) & 1;
    int ic = t >> 7;                              // 0..2

    int dlo = kd ? 0 : 1, dhi = kd ? 1 : 3;
    int hlo = kh ? 0 : 1, hhi = kh ? 1 : 3;
    int wlo = kw ? 0 : 1, whi = kw ? 1 : 3;
    const float* w = cw + (ic * 16 + oc) * 27;    // (ic, oc, 3,3,3)
    float s = 0.f;
    for (int i = dlo; i < dhi; i++)
        for (int j = hlo; j < hhi; j++)
            for (int k = wlo; k < whi; k++)
                s += w[i * 9 + j * 3 + k];
    g_wS[ic][kh][kd][kw][oc] = s * 0.0625f;       // SCALE1*SCALE2*0.125
    if (t < 16)
        g_fbS[t] = cb[t] * 0.5f + eb[t];          // (cb*SCALE1 + ext)*SCALE2
}

// od-quad blocking: thread computes 4 od x 16 oc (8 oc-pairs) x 1 w.
// acc[odd][p] = (out_oc2p, out_oc2p+1) at od = od0+odd, w = wbase+lane.
// Each LDS.128 weight load (2 oc-pairs) feeds 8 fma2 (x4 od amortization).
// Block = 32(lane) x 8(oh). Grid.x = wt*16 + ohtile (wt 0..3),
// grid.y = od-quad (0..31), grid.z = n.
__global__ void __launch_bounds__(256, 2)
conv_main(const float* __restrict__ x, float* __restrict__ out) {
    __shared__ __align__(16) float smw[3][2][2][2][16];
    __shared__ __align__(8)  float smb[16];

    int tid = threadIdx.y * 32 + threadIdx.x;
    {
        const float* gw = (const float*)g_wS;
        float* sw = (float*)smw;
        for (int i = tid; i < 384; i += 256) sw[i] = gw[i];
        if (tid < 16) smb[tid] = g_fbS[tid];
    }
    __syncthreads();

    int lane = threadIdx.x;
    int wt = blockIdx.x >> 4;                  // 0..3
    int oh = (blockIdx.x & 15) * 8 + threadIdx.y;
    if (oh >= ODIM) return;
    int od0 = blockIdx.y * 4;                  // 0,4,...,124
    int n   = blockIdx.z;
    int wbase = wt * 32;
    bool lastlane = (lane == 31);
    bool tailq = (od0 == 124);                 // rows od0+4 = 128 OOB; odd=3 invalid
    bool uguard = !(lastlane && wt == 3);      // lane31 u-load OOB guard at w=127

    const float* xb = x + (size_t)n * IC * C_STR
                        + (size_t)od0 * D_STR
                        + (size_t)oh * H_STR + wbase + lane;
    float* ob = out + (size_t)n * OC * O_CSTR
                    + (size_t)od0 * O_DSTR
                    + (size_t)oh * O_HSTR + wbase + lane;

    // acc[odd][p]: odd = od offset 0..3, p = oc pair (2p, 2p+1)
    ull acc[4][8];
#pragma unroll
    for (int p = 0; p < 8; p++) {
        ull b = *(const ull*)&smb[2 * p];
        acc[0][p] = b; acc[1][p] = b; acc[2][p] = b; acc[3][p] = b;
    }

#pragma unroll
    for (int ic = 0; ic < IC; ic++) {
#pragma unroll
        for (int kh = 0; kh < 2; kh++) {
            const float* rp = xb + (size_t)ic * C_STR + (size_t)kh * H_STR;

            // Load 5 od-planes' rows; build dup-pairs A (x[w]) and B (x[w+1]).
            ull A[5], B[5];
#pragma unroll
            for (int j = 0; j < 5; j++) {
                float v = 0.f, ue = 0.f;
                bool ok = !(tailq && j == 4);
                if (ok) {
                    const float* row = rp + (size_t)j * D_STR;
                    v = row[0];                        // x[wbase+lane]
                    if (lastlane && uguard) ue = row[1]; // x[wbase+32]
                }
                float u = __shfl_down_sync(0xffffffffu, v, 1);
                if (lastlane) u = ue;
                A[j] = pack2(v, v);
                B[j] = pack2(u, u);
            }

#pragma unroll
            for (int kd = 0; kd < 2; kd++) {
                const ulonglong2* W0 =
                    (const ulonglong2*)&smw[ic][kh][kd][0][0];
                const ulonglong2* W1 =
                    (const ulonglong2*)&smw[ic][kh][kd][1][0];
#pragma unroll
                for (int q = 0; q < 4; q++) {
                    ulonglong2 w0 = W0[q];     // kw=0, oc pairs 2q, 2q+1
                    ulonglong2 w1 = W1[q];     // kw=1
#pragma unroll
                    for (int odd = 0; odd < 4; odd++) {
                        int r = odd + kd;
                        acc[odd][2*q]   = fma2(A[r], w0.x, acc[odd][2*q]);
                        acc[odd][2*q+1] = fma2(A[r], w0.y, acc[odd][2*q+1]);
                        acc[odd][2*q]   = fma2(B[r], w1.x, acc[odd][2*q]);
                        acc[odd][2*q+1] = fma2(B[r], w1.y, acc[odd][2*q+1]);
                    }
                }
            }
        }
    }

    // Stores: skip w=127 (wt==3, lane31) and od=127 (tail quad odd==3).
    bool skipw = lastlane && (wt == 3);
#pragma unroll
    for (int odd = 0; odd < 4; odd++) {
        if (tailq && odd == 3) break;
        if (skipw) continue;
        float* o = ob + (size_t)odd * O_DSTR;
#pragma unroll
        for (int p = 0; p < 8; p++) {
            float2 a = unpack2(acc[odd][p]);
            __stcs(o + (size_t)(2 * p)     * O_CSTR, a.x);
            __stcs(o + (size_t)(2 * p + 1) * O_CSTR, a.y);
        }
    }
}

extern "C" void kernel_launch(void* const* d_in, const int* in_sizes, int n_in,
                              void* d_out, int out_size) {
    const float* x  = (const float*)d_in[0];
    const float* cw = (const float*)d_in[1];
    const float* cb = (const float*)d_in[2];
    const float* eb = (const float*)d_in[3];
    float* out = (float*)d_out;

    prep_kernel<<<1, 384>>>(cw, cb, eb);

    dim3 block(32, 8, 1);
    dim3 grid(64, 32, NB);    // x: 4 w-tiles * 16 oh-tiles, y: 32 od-quads, z: n
    conv_main<<<grid, block>>>(x, out);
}